// round 12
// baseline (speedup 1.0000x reference)
#include <cuda_runtime.h>
#include <cuda_bf16.h>

// Problem constants
#define B_DIM 16
#define T_DIM 100
#define FRAME_INTS 3888         // 27*48*3
#define NBINS 512
#define WIN 101
#define HALF 50
#define ODIM 128

// Scratch (device globals — no allocation allowed)
__device__ int   g_histi[B_DIM * T_DIM * NBINS];  // int counts (zero-init; k_norm re-zeroes)
__device__ float g_hist [B_DIM * T_DIM * NBINS];  // normalized
__device__ float g_sim  [B_DIM * T_DIM * T_DIM];

// ---- f32x2 packed-FMA helpers (FFMA2) --------------------------------------
__device__ __forceinline__ void ffma2(unsigned long long& d,
                                      unsigned long long a,
                                      unsigned long long b) {
    asm("fma.rn.f32x2 %0, %1, %2, %0;" : "+l"(d) : "l"(a), "l"(b));
}
__device__ __forceinline__ float2 f2unpack(unsigned long long u) {
    float2 f;
    asm("mov.b64 {%0, %1}, %2;" : "=f"(f.x), "=f"(f.y) : "l"(u));
    return f;
}
__device__ __forceinline__ unsigned long long f2pack(float a, float b) {
    unsigned long long u;
    asm("mov.b64 %0, {%1, %2};" : "=l"(u) : "f"(a), "f"(b));
    return u;
}

// ---------------------------------------------------------------------------
// Kernel 1a: binning via global reductions (REDG — fire-and-forget, no smem,
// no barriers; loads stream at full BW while L2 atomic units absorb the adds).
// ---------------------------------------------------------------------------
__global__ __launch_bounds__(256) void k_hist(const int* __restrict__ frames,
                                              int* __restrict__ histi) {
    const int f   = blockIdx.x;
    const int tid = threadIdx.x;

    int* h = histi + (long long)f * NBINS;
    const int4* base = reinterpret_cast<const int4*>(frames + (long long)f * FRAME_INTS);

    for (int c = tid; c < 324; c += 256) {
        int4 a = base[3*c+0];
        int4 b = base[3*c+1];
        int4 d = base[3*c+2];
        atomicAdd(&h[((a.x >> 5) << 6) | ((a.y >> 5) << 3) | (a.z >> 5)], 1);
        atomicAdd(&h[((a.w >> 5) << 6) | ((b.x >> 5) << 3) | (b.y >> 5)], 1);
        atomicAdd(&h[((b.z >> 5) << 6) | ((b.w >> 5) << 3) | (d.x >> 5)], 1);
        atomicAdd(&h[((d.y >> 5) << 6) | ((d.z >> 5) << 3) | (d.w >> 5)], 1);
    }
}

// ---------------------------------------------------------------------------
// Kernel 1b: per-frame L2 normalize + re-zero the int counts (keeps g_histi
// clean for the next graph replay without a memset node).
// ---------------------------------------------------------------------------
__global__ __launch_bounds__(128) void k_norm(int* __restrict__ histi,
                                              float* __restrict__ hist) {
    __shared__ int wsum[4];
    __shared__ float s_inv;

    const int f   = blockIdx.x;
    const int tid = threadIdx.x;

    int4* hi = reinterpret_cast<int4*>(histi + (long long)f * NBINS);
    int4 v = hi[tid];                     // 128 threads x int4 = 512 bins

    int local = v.x*v.x + v.y*v.y + v.z*v.z + v.w*v.w;   // exact (<2^31)
    #pragma unroll
    for (int o = 16; o; o >>= 1) local += __shfl_down_sync(0xffffffff, local, o);
    if ((tid & 31) == 0) wsum[tid >> 5] = local;
    __syncthreads();
    if (tid == 0)
        s_inv = 1.0f / sqrtf((float)(wsum[0] + wsum[1] + wsum[2] + wsum[3]));
    __syncthreads();

    const float inv = s_inv;
    float4 o = make_float4((float)v.x * inv, (float)v.y * inv,
                           (float)v.z * inv, (float)v.w * inv);
    reinterpret_cast<float4*>(hist + (long long)f * NBINS)[tid] = o;
    hi[tid] = make_int4(0, 0, 0, 0);      // self-clean for next replay
}

// ---------------------------------------------------------------------------
// Kernel 2: sim[b] = X[b] @ X[b]^T, banded + symmetric.  (R9 — unchanged)
// ---------------------------------------------------------------------------
__constant__ int c_ti[9] = {0,0,0,1,1,1,2,2,3};
__constant__ int c_tj[9] = {0,1,2,1,2,3,2,3,3};

#define CH_STRIDE 132                              // 128 + 4 pad
#define SIM_SMEM_FLOATS (2*2*32*CH_STRIDE + 4*32*36)
#define SIM_SMEM_BYTES  (SIM_SMEM_FLOATS * 4)      // 86016 B

__global__ __launch_bounds__(512) void k_sim(const float* __restrict__ hist,
                                             float* __restrict__ sim) {
    extern __shared__ __align__(16) float sm[];
    float* A_s = sm;                               // [2][32][132]
    float* B_s = sm + 2 * 32 * CH_STRIDE;          // [2][32][132]
    float* red = sm + 4 * 32 * CH_STRIDE;          // [4][32][36]

    const int b  = blockIdx.y;
    const int tl = blockIdx.x;
    const int ti = c_ti[tl], tj = c_tj[tl];
    const bool diag = (ti == tj);

    const int row0 = ti * 32;
    const int col0 = tj * 32;
    const float* X = hist + (long long)b * T_DIM * NBINS;
    const int tid = threadIdx.x;

    const float* pa[2];
    const float* pb[2];
    int   srow[2];
    int   scol[2];
    #pragma unroll
    for (int j = 0; j < 2; j++) {
        int idx = tid + j * 512;
        srow[j] = idx >> 5;
        scol[j] = (idx & 31) << 2;
        pa[j] = X + min(row0 + srow[j], T_DIM - 1) * NBINS + scol[j];
        pb[j] = X + min(col0 + srow[j], T_DIM - 1) * NBINS + scol[j];
    }

    float4 ra[2], rb[2];
    #pragma unroll
    for (int j = 0; j < 2; j++) {
        ra[j] = *reinterpret_cast<const float4*>(pa[j]);
        if (!diag) rb[j] = *reinterpret_cast<const float4*>(pb[j]);
    }
    #pragma unroll
    for (int j = 0; j < 2; j++) {
        *reinterpret_cast<float4*>(A_s + srow[j] * CH_STRIDE + scol[j]) = ra[j];
        if (!diag)
            *reinterpret_cast<float4*>(B_s + srow[j] * CH_STRIDE + scol[j]) = rb[j];
    }
    __syncthreads();

    const int w    = tid >> 5;
    const int lane = tid & 31;
    const int q    = w >> 2;
    const int wc   = w & 3;
    const int r0   = lane & 15;
    const int rh   = lane >> 4;
    const int cb   = 8 * wc + 4 * rh;

    unsigned long long acc[8];
    #pragma unroll
    for (int i = 0; i < 8; i++) acc[i] = 0ull;

    #pragma unroll
    for (int ch = 0; ch < 4; ch++) {
        const int buf = ch & 1;
        float* Ab = A_s + buf * (32 * CH_STRIDE);
        float* Bb = diag ? Ab : (B_s + buf * (32 * CH_STRIDE));

        if (ch < 3) {
            const int kc = (ch + 1) * 128;
            #pragma unroll
            for (int j = 0; j < 2; j++) {
                ra[j] = *reinterpret_cast<const float4*>(pa[j] + kc);
                if (!diag) rb[j] = *reinterpret_cast<const float4*>(pb[j] + kc);
            }
        }

        const float* a0 = Ab + r0 * CH_STRIDE + 32 * q;
        const float* a1 = a0 + 16 * CH_STRIDE;
        const float* b0 = Bb + cb * CH_STRIDE + 32 * q;
        const float* b1 = b0 + CH_STRIDE;
        const float* b2 = b1 + CH_STRIDE;
        const float* b3 = b2 + CH_STRIDE;

        #pragma unroll
        for (int k = 0; k < 32; k += 4) {
            ulonglong2 aL = *reinterpret_cast<const ulonglong2*>(a0 + k);
            ulonglong2 aH = *reinterpret_cast<const ulonglong2*>(a1 + k);
            ulonglong2 q0 = *reinterpret_cast<const ulonglong2*>(b0 + k);
            ulonglong2 q1 = *reinterpret_cast<const ulonglong2*>(b1 + k);
            ulonglong2 q2 = *reinterpret_cast<const ulonglong2*>(b2 + k);
            ulonglong2 q3 = *reinterpret_cast<const ulonglong2*>(b3 + k);

            ffma2(acc[0], aL.x, q0.x); ffma2(acc[0], aL.y, q0.y);
            ffma2(acc[1], aL.x, q1.x); ffma2(acc[1], aL.y, q1.y);
            ffma2(acc[2], aL.x, q2.x); ffma2(acc[2], aL.y, q2.y);
            ffma2(acc[3], aL.x, q3.x); ffma2(acc[3], aL.y, q3.y);
            ffma2(acc[4], aH.x, q0.x); ffma2(acc[4], aH.y, q0.y);
            ffma2(acc[5], aH.x, q1.x); ffma2(acc[5], aH.y, q1.y);
            ffma2(acc[6], aH.x, q2.x); ffma2(acc[6], aH.y, q2.y);
            ffma2(acc[7], aH.x, q3.x); ffma2(acc[7], aH.y, q3.y);
        }

        if (ch < 3) {
            __syncthreads();
            const int nb = (ch + 1) & 1;
            float* An = A_s + nb * (32 * CH_STRIDE);
            float* Bn = B_s + nb * (32 * CH_STRIDE);
            #pragma unroll
            for (int j = 0; j < 2; j++) {
                *reinterpret_cast<float4*>(An + srow[j] * CH_STRIDE + scol[j]) = ra[j];
                if (!diag)
                    *reinterpret_cast<float4*>(Bn + srow[j] * CH_STRIDE + scol[j]) = rb[j];
            }
            __syncthreads();
        }
    }

    #pragma unroll
    for (int rr = 0; rr < 2; rr++) {
        #pragma unroll
        for (int cc = 0; cc < 4; cc++) {
            float2 f = f2unpack(acc[rr * 4 + cc]);
            red[(q * 32 + r0 + 16 * rr) * 36 + cb + cc] = f.x + f.y;
        }
    }
    __syncthreads();

    float* S = sim + (long long)b * T_DIM * T_DIM;
    #pragma unroll
    for (int j = 0; j < 2; j++) {
        int o = tid + j * 512;
        int r = o >> 5, c = o & 31;
        float v = red[(r     ) * 36 + c] + red[(32 + r) * 36 + c]
                + red[(64 + r) * 36 + c] + red[(96 + r) * 36 + c];
        int gr = row0 + r, gc = col0 + c;
        if (gr < T_DIM && gc < T_DIM) {
            S[gr * T_DIM + gc] = v;
            S[gc * T_DIM + gr] = v;
        }
    }
}

// ---------------------------------------------------------------------------
// Kernel 3: band extraction + FC + ReLU.  (R9 — unchanged)
// ---------------------------------------------------------------------------
#define FC_W_FLOATS  (WIN * ODIM)             // 12928
#define FC_BT_OFF    FC_W_FLOATS              // band_t [104][12]
#define FC_SCR_OFF   (FC_W_FLOATS + 104 * 12)
#define FC_SMEM_FLOATS (FC_SCR_OFF + 3 * 10 * ODIM)
#define FC_SMEM_BYTES  (FC_SMEM_FLOATS * 4)

__global__ __launch_bounds__(512) void k_fc(const float* __restrict__ sim,
                                            const float* __restrict__ fc_w,
                                            const float* __restrict__ fc_b,
                                            float* __restrict__ out) {
    extern __shared__ __align__(16) float dyn[];
    float* w_s    = dyn;                 // [101][128]
    float* band_t = dyn + FC_BT_OFF;     // [s][12]
    float* scr    = dyn + FC_SCR_OFF;    // [3][10][128]

    const int b   = blockIdx.y;
    const int t0  = blockIdx.x * 10;
    const int tid = threadIdx.x;
    const int d   = tid & 127;
    const int q   = tid >> 7;

    {
        const float4* src = reinterpret_cast<const float4*>(fc_w);
        float4* dst = reinterpret_cast<float4*>(w_s);
        for (int i = tid; i < FC_W_FLOATS / 4; i += 512) dst[i] = src[i];
    }

    const float* S = sim + (long long)b * T_DIM * T_DIM;
    for (int i = tid; i < 10 * WIN; i += 512) {
        int tt = i / WIN, s = i - tt * WIN;
        int t  = t0 + tt;
        int t2 = t + s - HALF;
        band_t[s * 12 + tt] = (t2 >= 0 && t2 < T_DIM) ? S[t * T_DIM + t2] : 0.f;
    }
    __syncthreads();

    const int s0 = q * 26;
    const int s1 = min(WIN, s0 + 26);

    unsigned long long acc2[5];
    #pragma unroll
    for (int i = 0; i < 5; i++) acc2[i] = 0ull;

    const float* wp = w_s + d;
    for (int s = s0; s < s1; s++) {
        float wv = wp[s * ODIM];
        unsigned long long ww = f2pack(wv, wv);
        const float* bt = band_t + s * 12;
        ulonglong2 p01 = *reinterpret_cast<const ulonglong2*>(bt);
        ulonglong2 p23 = *reinterpret_cast<const ulonglong2*>(bt + 4);
        unsigned long long p4 = *reinterpret_cast<const unsigned long long*>(bt + 8);
        ffma2(acc2[0], ww, p01.x);
        ffma2(acc2[1], ww, p01.y);
        ffma2(acc2[2], ww, p23.x);
        ffma2(acc2[3], ww, p23.y);
        ffma2(acc2[4], ww, p4);
    }

    float acc[10];
    #pragma unroll
    for (int p = 0; p < 5; p++) {
        float2 f = f2unpack(acc2[p]);
        acc[2 * p]     = f.x;
        acc[2 * p + 1] = f.y;
    }

    if (q) {
        float* sc = scr + (q - 1) * (10 * ODIM);
        #pragma unroll
        for (int tt = 0; tt < 10; tt++) sc[tt * ODIM + d] = acc[tt];
    }
    __syncthreads();

    if (q == 0) {
        const float bias = fc_b[d];
        float* O = out + ((long long)(b * T_DIM + t0)) * ODIM + d;
        #pragma unroll
        for (int tt = 0; tt < 10; tt++) {
            float v = acc[tt] + bias
                    + scr[0 * (10*ODIM) + tt * ODIM + d]
                    + scr[1 * (10*ODIM) + tt * ODIM + d]
                    + scr[2 * (10*ODIM) + tt * ODIM + d];
            O[tt * ODIM] = fmaxf(v, 0.f);
        }
    }
}

// ---------------------------------------------------------------------------
extern "C" void kernel_launch(void* const* d_in, const int* in_sizes, int n_in,
                              void* d_out, int out_size) {
    const int*   frames = (const int*)  d_in[0];
    const float* fc_w   = (const float*)d_in[1];
    const float* fc_b   = (const float*)d_in[2];
    float*       out    = (float*)d_out;

    int*   histi;
    float* hist;
    float* sim;
    cudaGetSymbolAddress((void**)&histi, g_histi);
    cudaGetSymbolAddress((void**)&hist,  g_hist);
    cudaGetSymbolAddress((void**)&sim,   g_sim);

    cudaFuncSetAttribute(k_sim, cudaFuncAttributeMaxDynamicSharedMemorySize,
                         SIM_SMEM_BYTES);
    cudaFuncSetAttribute(k_fc, cudaFuncAttributeMaxDynamicSharedMemorySize,
                         FC_SMEM_BYTES);

    k_hist<<<B_DIM * T_DIM, 256>>>(frames, histi);
    k_norm<<<B_DIM * T_DIM, 128>>>(histi, hist);
    k_sim <<<dim3(9, B_DIM), 512, SIM_SMEM_BYTES>>>(hist, sim);
    k_fc  <<<dim3(T_DIM / 10, B_DIM), 512, FC_SMEM_BYTES>>>(sim, fc_w, fc_b, out);
}

// round 13
// speedup vs baseline: 1.3679x; 1.3679x over previous
#include <cuda_runtime.h>
#include <cuda_bf16.h>

// Problem constants
#define B_DIM 16
#define T_DIM 100
#define FRAME_INTS 3888         // 27*48*3
#define NBINS 512
#define WIN 101
#define HALF 50
#define ODIM 128
#define TG 5                    // t's per k_fc block

// Scratch (device globals — no allocation allowed)
__device__ float g_hist[B_DIM * T_DIM * NBINS];   // 3.28 MB
__device__ float g_sim [B_DIM * T_DIM * T_DIM];   // 640 KB

// ---- f32x2 packed-FMA helpers (FFMA2) --------------------------------------
__device__ __forceinline__ void ffma2(unsigned long long& d,
                                      unsigned long long a,
                                      unsigned long long b) {
    asm("fma.rn.f32x2 %0, %1, %2, %0;" : "+l"(d) : "l"(a), "l"(b));
}
__device__ __forceinline__ float2 f2unpack(unsigned long long u) {
    float2 f;
    asm("mov.b64 {%0, %1}, %2;" : "=f"(f.x), "=f"(f.y) : "l"(u));
    return f;
}
__device__ __forceinline__ unsigned long long f2pack(float a, float b) {
    unsigned long long u;
    asm("mov.b64 %0, {%1, %2};" : "=l"(u) : "f"(a), "f"(b));
    return u;
}

// ---------------------------------------------------------------------------
// Kernel 1: per-frame 512-bin color histogram + L2 normalize. (R9/R5 —
// at the smem-atomic throughput floor; 6 variants tried, all ~9.5us.)
// ---------------------------------------------------------------------------
__global__ __launch_bounds__(256) void k_hist(const int* __restrict__ frames,
                                              float* __restrict__ hist) {
    __shared__ int sh[NBINS];
    __shared__ int wsum[8];
    __shared__ float s_inv;

    const int f   = blockIdx.x;
    const int tid = threadIdx.x;

    for (int i = tid; i < NBINS; i += 256) sh[i] = 0;
    __syncthreads();

    const int4* base = reinterpret_cast<const int4*>(frames + (long long)f * FRAME_INTS);
    for (int c = tid; c < 324; c += 256) {
        int4 a = base[3*c+0];
        int4 b = base[3*c+1];
        int4 d = base[3*c+2];
        atomicAdd(&sh[((a.x >> 5) << 6) | ((a.y >> 5) << 3) | (a.z >> 5)], 1);
        atomicAdd(&sh[((a.w >> 5) << 6) | ((b.x >> 5) << 3) | (b.y >> 5)], 1);
        atomicAdd(&sh[((b.z >> 5) << 6) | ((b.w >> 5) << 3) | (d.x >> 5)], 1);
        atomicAdd(&sh[((d.y >> 5) << 6) | ((d.z >> 5) << 3) | (d.w >> 5)], 1);
    }
    __syncthreads();

    int local = 0;
    for (int i = tid; i < NBINS; i += 256) { int h = sh[i]; local += h * h; }
    #pragma unroll
    for (int o = 16; o; o >>= 1) local += __shfl_down_sync(0xffffffff, local, o);
    if ((tid & 31) == 0) wsum[tid >> 5] = local;
    __syncthreads();
    if (tid == 0) {
        int tot = 0;
        #pragma unroll
        for (int w = 0; w < 8; w++) tot += wsum[w];
        s_inv = 1.0f / sqrtf((float)tot);
    }
    __syncthreads();

    const float inv = s_inv;
    float* out = hist + (long long)f * NBINS;
    for (int i = tid; i < NBINS; i += 256) out[i] = (float)sh[i] * inv;
}

// ---------------------------------------------------------------------------
// Kernel 2: sim[b] = X[b] @ X[b]^T, banded + symmetric.  (R9 — unchanged)
// ---------------------------------------------------------------------------
__constant__ int c_ti[9] = {0,0,0,1,1,1,2,2,3};
__constant__ int c_tj[9] = {0,1,2,1,2,3,2,3,3};

#define CH_STRIDE 132                              // 128 + 4 pad
#define SIM_SMEM_FLOATS (2*2*32*CH_STRIDE + 4*32*36)
#define SIM_SMEM_BYTES  (SIM_SMEM_FLOATS * 4)      // 86016 B

__global__ __launch_bounds__(512) void k_sim(const float* __restrict__ hist,
                                             float* __restrict__ sim) {
    extern __shared__ __align__(16) float sm[];
    float* A_s = sm;                               // [2][32][132]
    float* B_s = sm + 2 * 32 * CH_STRIDE;          // [2][32][132]
    float* red = sm + 4 * 32 * CH_STRIDE;          // [4][32][36]

    const int b  = blockIdx.y;
    const int tl = blockIdx.x;
    const int ti = c_ti[tl], tj = c_tj[tl];
    const bool diag = (ti == tj);

    const int row0 = ti * 32;
    const int col0 = tj * 32;
    const float* X = hist + (long long)b * T_DIM * NBINS;
    const int tid = threadIdx.x;

    const float* pa[2];
    const float* pb[2];
    int   srow[2];
    int   scol[2];
    #pragma unroll
    for (int j = 0; j < 2; j++) {
        int idx = tid + j * 512;
        srow[j] = idx >> 5;
        scol[j] = (idx & 31) << 2;
        pa[j] = X + min(row0 + srow[j], T_DIM - 1) * NBINS + scol[j];
        pb[j] = X + min(col0 + srow[j], T_DIM - 1) * NBINS + scol[j];
    }

    float4 ra[2], rb[2];
    #pragma unroll
    for (int j = 0; j < 2; j++) {
        ra[j] = *reinterpret_cast<const float4*>(pa[j]);
        if (!diag) rb[j] = *reinterpret_cast<const float4*>(pb[j]);
    }
    #pragma unroll
    for (int j = 0; j < 2; j++) {
        *reinterpret_cast<float4*>(A_s + srow[j] * CH_STRIDE + scol[j]) = ra[j];
        if (!diag)
            *reinterpret_cast<float4*>(B_s + srow[j] * CH_STRIDE + scol[j]) = rb[j];
    }
    __syncthreads();

    const int w    = tid >> 5;
    const int lane = tid & 31;
    const int q    = w >> 2;
    const int wc   = w & 3;
    const int r0   = lane & 15;
    const int rh   = lane >> 4;
    const int cb   = 8 * wc + 4 * rh;

    unsigned long long acc[8];
    #pragma unroll
    for (int i = 0; i < 8; i++) acc[i] = 0ull;

    #pragma unroll
    for (int ch = 0; ch < 4; ch++) {
        const int buf = ch & 1;
        float* Ab = A_s + buf * (32 * CH_STRIDE);
        float* Bb = diag ? Ab : (B_s + buf * (32 * CH_STRIDE));

        if (ch < 3) {
            const int kc = (ch + 1) * 128;
            #pragma unroll
            for (int j = 0; j < 2; j++) {
                ra[j] = *reinterpret_cast<const float4*>(pa[j] + kc);
                if (!diag) rb[j] = *reinterpret_cast<const float4*>(pb[j] + kc);
            }
        }

        const float* a0 = Ab + r0 * CH_STRIDE + 32 * q;
        const float* a1 = a0 + 16 * CH_STRIDE;
        const float* b0 = Bb + cb * CH_STRIDE + 32 * q;
        const float* b1 = b0 + CH_STRIDE;
        const float* b2 = b1 + CH_STRIDE;
        const float* b3 = b2 + CH_STRIDE;

        #pragma unroll
        for (int k = 0; k < 32; k += 4) {
            ulonglong2 aL = *reinterpret_cast<const ulonglong2*>(a0 + k);
            ulonglong2 aH = *reinterpret_cast<const ulonglong2*>(a1 + k);
            ulonglong2 q0 = *reinterpret_cast<const ulonglong2*>(b0 + k);
            ulonglong2 q1 = *reinterpret_cast<const ulonglong2*>(b1 + k);
            ulonglong2 q2 = *reinterpret_cast<const ulonglong2*>(b2 + k);
            ulonglong2 q3 = *reinterpret_cast<const ulonglong2*>(b3 + k);

            ffma2(acc[0], aL.x, q0.x); ffma2(acc[0], aL.y, q0.y);
            ffma2(acc[1], aL.x, q1.x); ffma2(acc[1], aL.y, q1.y);
            ffma2(acc[2], aL.x, q2.x); ffma2(acc[2], aL.y, q2.y);
            ffma2(acc[3], aL.x, q3.x); ffma2(acc[3], aL.y, q3.y);
            ffma2(acc[4], aH.x, q0.x); ffma2(acc[4], aH.y, q0.y);
            ffma2(acc[5], aH.x, q1.x); ffma2(acc[5], aH.y, q1.y);
            ffma2(acc[6], aH.x, q2.x); ffma2(acc[6], aH.y, q2.y);
            ffma2(acc[7], aH.x, q3.x); ffma2(acc[7], aH.y, q3.y);
        }

        if (ch < 3) {
            __syncthreads();
            const int nb = (ch + 1) & 1;
            float* An = A_s + nb * (32 * CH_STRIDE);
            float* Bn = B_s + nb * (32 * CH_STRIDE);
            #pragma unroll
            for (int j = 0; j < 2; j++) {
                *reinterpret_cast<float4*>(An + srow[j] * CH_STRIDE + scol[j]) = ra[j];
                if (!diag)
                    *reinterpret_cast<float4*>(Bn + srow[j] * CH_STRIDE + scol[j]) = rb[j];
            }
            __syncthreads();
        }
    }

    #pragma unroll
    for (int rr = 0; rr < 2; rr++) {
        #pragma unroll
        for (int cc = 0; cc < 4; cc++) {
            float2 f = f2unpack(acc[rr * 4 + cc]);
            red[(q * 32 + r0 + 16 * rr) * 36 + cb + cc] = f.x + f.y;
        }
    }
    __syncthreads();

    float* S = sim + (long long)b * T_DIM * T_DIM;
    #pragma unroll
    for (int j = 0; j < 2; j++) {
        int o = tid + j * 512;
        int r = o >> 5, c = o & 31;
        float v = red[(r     ) * 36 + c] + red[(32 + r) * 36 + c]
                + red[(64 + r) * 36 + c] + red[(96 + r) * 36 + c];
        int gr = row0 + r, gc = col0 + c;
        if (gr < T_DIM && gc < T_DIM) {
            S[gr * T_DIM + gc] = v;
            S[gc * T_DIM + gr] = v;
        }
    }
}

// ---------------------------------------------------------------------------
// Kernel 3: band extraction + FC + ReLU.
// TG=5 t's per block -> 320 blocks (~2.2/SM, up to 3 co-resident by smem)
// so cross-block scheduling hides the weight-load/LDS latency chains.
// 512 threads = (d in 128) x (q = s-quarter); band transposed [s][8].
// ---------------------------------------------------------------------------
#define FC_W_FLOATS  (WIN * ODIM)             // 12928
#define FC_BT_OFF    FC_W_FLOATS              // band_t [104][8]
#define FC_SCR_OFF   (FC_W_FLOATS + 104 * 8)
#define FC_SMEM_FLOATS (FC_SCR_OFF + 3 * TG * ODIM)
#define FC_SMEM_BYTES  (FC_SMEM_FLOATS * 4)   // ~62.7 KB

__global__ __launch_bounds__(512) void k_fc(const float* __restrict__ sim,
                                            const float* __restrict__ fc_w,
                                            const float* __restrict__ fc_b,
                                            float* __restrict__ out) {
    extern __shared__ __align__(16) float dyn[];
    float* w_s    = dyn;                 // [101][128]
    float* band_t = dyn + FC_BT_OFF;     // [s][8] (t 0..4 used)
    float* scr    = dyn + FC_SCR_OFF;    // [3][TG][128]

    const int b   = blockIdx.y;
    const int t0  = blockIdx.x * TG;
    const int tid = threadIdx.x;
    const int d   = tid & 127;
    const int q   = tid >> 7;

    {
        const float4* src = reinterpret_cast<const float4*>(fc_w);
        float4* dst = reinterpret_cast<float4*>(w_s);
        for (int i = tid; i < FC_W_FLOATS / 4; i += 512) dst[i] = src[i];
    }

    const float* S = sim + (long long)b * T_DIM * T_DIM;
    for (int i = tid; i < TG * WIN; i += 512) {
        int tt = i / WIN, s = i - tt * WIN;
        int t  = t0 + tt;
        int t2 = t + s - HALF;
        band_t[s * 8 + tt] = (t2 >= 0 && t2 < T_DIM) ? S[t * T_DIM + t2] : 0.f;
    }
    __syncthreads();

    const int s0 = q * 26;
    const int s1 = min(WIN, s0 + 26);

    unsigned long long acc2[2] = {0ull, 0ull};   // t pairs (0,1) (2,3)
    float acc4 = 0.f;                            // t 4

    const float* wp = w_s + d;
    for (int s = s0; s < s1; s++) {
        float wv = wp[s * ODIM];
        unsigned long long ww = f2pack(wv, wv);
        const float* bt = band_t + s * 8;
        ulonglong2 p01 = *reinterpret_cast<const ulonglong2*>(bt);  // t0..t3
        float b4 = bt[4];
        ffma2(acc2[0], ww, p01.x);
        ffma2(acc2[1], ww, p01.y);
        acc4 = fmaf(wv, b4, acc4);
    }

    float acc[TG];
    {
        float2 f0 = f2unpack(acc2[0]);
        float2 f1 = f2unpack(acc2[1]);
        acc[0] = f0.x; acc[1] = f0.y;
        acc[2] = f1.x; acc[3] = f1.y;
        acc[4] = acc4;
    }

    if (q) {
        float* sc = scr + (q - 1) * (TG * ODIM);
        #pragma unroll
        for (int tt = 0; tt < TG; tt++) sc[tt * ODIM + d] = acc[tt];
    }
    __syncthreads();

    if (q == 0) {
        const float bias = fc_b[d];
        float* O = out + ((long long)(b * T_DIM + t0)) * ODIM + d;
        #pragma unroll
        for (int tt = 0; tt < TG; tt++) {
            float v = acc[tt] + bias
                    + scr[0 * (TG*ODIM) + tt * ODIM + d]
                    + scr[1 * (TG*ODIM) + tt * ODIM + d]
                    + scr[2 * (TG*ODIM) + tt * ODIM + d];
            O[tt * ODIM] = fmaxf(v, 0.f);
        }
    }
}

// ---------------------------------------------------------------------------
extern "C" void kernel_launch(void* const* d_in, const int* in_sizes, int n_in,
                              void* d_out, int out_size) {
    const int*   frames = (const int*)  d_in[0];
    const float* fc_w   = (const float*)d_in[1];
    const float* fc_b   = (const float*)d_in[2];
    float*       out    = (float*)d_out;

    float* hist;
    float* sim;
    cudaGetSymbolAddress((void**)&hist, g_hist);
    cudaGetSymbolAddress((void**)&sim,  g_sim);

    cudaFuncSetAttribute(k_sim, cudaFuncAttributeMaxDynamicSharedMemorySize,
                         SIM_SMEM_BYTES);
    cudaFuncSetAttribute(k_fc, cudaFuncAttributeMaxDynamicSharedMemorySize,
                         FC_SMEM_BYTES);

    k_hist<<<B_DIM * T_DIM, 256>>>(frames, hist);
    k_sim <<<dim3(9, B_DIM), 512, SIM_SMEM_BYTES>>>(hist, sim);
    k_fc  <<<dim3(T_DIM / TG, B_DIM), 512, FC_SMEM_BYTES>>>(sim, fc_w, fc_b, out);
}

// round 14
// speedup vs baseline: 1.4458x; 1.0569x over previous
#include <cuda_runtime.h>
#include <cuda_bf16.h>

// Problem constants
#define B_DIM 16
#define T_DIM 100
#define FRAME_INTS 3888         // 27*48*3
#define NBINS 512
#define WIN 101
#define HALF 50
#define ODIM 128
#define TG 5                    // t's per k_fc block

// Scratch (device globals — no allocation allowed)
__device__ float g_hist[B_DIM * T_DIM * NBINS];   // 3.28 MB
__device__ float g_sim [B_DIM * T_DIM * T_DIM];   // 640 KB

// ---- f32x2 packed-FMA helpers (FFMA2) --------------------------------------
__device__ __forceinline__ void ffma2(unsigned long long& d,
                                      unsigned long long a,
                                      unsigned long long b) {
    asm("fma.rn.f32x2 %0, %1, %2, %0;" : "+l"(d) : "l"(a), "l"(b));
}
__device__ __forceinline__ float2 f2unpack(unsigned long long u) {
    float2 f;
    asm("mov.b64 {%0, %1}, %2;" : "=f"(f.x), "=f"(f.y) : "l"(u));
    return f;
}
__device__ __forceinline__ unsigned long long f2pack(float a, float b) {
    unsigned long long u;
    asm("mov.b64 %0, {%1, %2};" : "=l"(u) : "f"(a), "f"(b));
    return u;
}

// ---------------------------------------------------------------------------
// Kernel 1: per-frame 512-bin color histogram + L2 normalize. (R9/R5 —
// at the smem-atomic throughput floor; 6 variants tried, all ~9.5us.)
// ---------------------------------------------------------------------------
__global__ __launch_bounds__(256) void k_hist(const int* __restrict__ frames,
                                              float* __restrict__ hist) {
    __shared__ int sh[NBINS];
    __shared__ int wsum[8];
    __shared__ float s_inv;

    const int f   = blockIdx.x;
    const int tid = threadIdx.x;

    for (int i = tid; i < NBINS; i += 256) sh[i] = 0;
    __syncthreads();

    const int4* base = reinterpret_cast<const int4*>(frames + (long long)f * FRAME_INTS);
    for (int c = tid; c < 324; c += 256) {
        int4 a = base[3*c+0];
        int4 b = base[3*c+1];
        int4 d = base[3*c+2];
        atomicAdd(&sh[((a.x >> 5) << 6) | ((a.y >> 5) << 3) | (a.z >> 5)], 1);
        atomicAdd(&sh[((a.w >> 5) << 6) | ((b.x >> 5) << 3) | (b.y >> 5)], 1);
        atomicAdd(&sh[((b.z >> 5) << 6) | ((b.w >> 5) << 3) | (d.x >> 5)], 1);
        atomicAdd(&sh[((d.y >> 5) << 6) | ((d.z >> 5) << 3) | (d.w >> 5)], 1);
    }
    __syncthreads();

    int local = 0;
    for (int i = tid; i < NBINS; i += 256) { int h = sh[i]; local += h * h; }
    #pragma unroll
    for (int o = 16; o; o >>= 1) local += __shfl_down_sync(0xffffffff, local, o);
    if ((tid & 31) == 0) wsum[tid >> 5] = local;
    __syncthreads();
    if (tid == 0) {
        int tot = 0;
        #pragma unroll
        for (int w = 0; w < 8; w++) tot += wsum[w];
        s_inv = 1.0f / sqrtf((float)tot);
    }
    __syncthreads();

    const float inv = s_inv;
    float* out = hist + (long long)f * NBINS;
    for (int i = tid; i < NBINS; i += 256) out[i] = (float)sh[i] * inv;
}

// ---------------------------------------------------------------------------
// Kernel 2: sim[b] = X[b] @ X[b]^T, banded + symmetric.  (R9 — unchanged)
// ---------------------------------------------------------------------------
__constant__ int c_ti[9] = {0,0,0,1,1,1,2,2,3};
__constant__ int c_tj[9] = {0,1,2,1,2,3,2,3,3};

#define CH_STRIDE 132                              // 128 + 4 pad
#define SIM_SMEM_FLOATS (2*2*32*CH_STRIDE + 4*32*36)
#define SIM_SMEM_BYTES  (SIM_SMEM_FLOATS * 4)      // 86016 B

__global__ __launch_bounds__(512) void k_sim(const float* __restrict__ hist,
                                             float* __restrict__ sim) {
    extern __shared__ __align__(16) float sm[];
    float* A_s = sm;                               // [2][32][132]
    float* B_s = sm + 2 * 32 * CH_STRIDE;          // [2][32][132]
    float* red = sm + 4 * 32 * CH_STRIDE;          // [4][32][36]

    const int b  = blockIdx.y;
    const int tl = blockIdx.x;
    const int ti = c_ti[tl], tj = c_tj[tl];
    const bool diag = (ti == tj);

    const int row0 = ti * 32;
    const int col0 = tj * 32;
    const float* X = hist + (long long)b * T_DIM * NBINS;
    const int tid = threadIdx.x;

    const float* pa[2];
    const float* pb[2];
    int   srow[2];
    int   scol[2];
    #pragma unroll
    for (int j = 0; j < 2; j++) {
        int idx = tid + j * 512;
        srow[j] = idx >> 5;
        scol[j] = (idx & 31) << 2;
        pa[j] = X + min(row0 + srow[j], T_DIM - 1) * NBINS + scol[j];
        pb[j] = X + min(col0 + srow[j], T_DIM - 1) * NBINS + scol[j];
    }

    float4 ra[2], rb[2];
    #pragma unroll
    for (int j = 0; j < 2; j++) {
        ra[j] = *reinterpret_cast<const float4*>(pa[j]);
        if (!diag) rb[j] = *reinterpret_cast<const float4*>(pb[j]);
    }
    #pragma unroll
    for (int j = 0; j < 2; j++) {
        *reinterpret_cast<float4*>(A_s + srow[j] * CH_STRIDE + scol[j]) = ra[j];
        if (!diag)
            *reinterpret_cast<float4*>(B_s + srow[j] * CH_STRIDE + scol[j]) = rb[j];
    }
    __syncthreads();

    const int w    = tid >> 5;
    const int lane = tid & 31;
    const int q    = w >> 2;
    const int wc   = w & 3;
    const int r0   = lane & 15;
    const int rh   = lane >> 4;
    const int cb   = 8 * wc + 4 * rh;

    unsigned long long acc[8];
    #pragma unroll
    for (int i = 0; i < 8; i++) acc[i] = 0ull;

    #pragma unroll
    for (int ch = 0; ch < 4; ch++) {
        const int buf = ch & 1;
        float* Ab = A_s + buf * (32 * CH_STRIDE);
        float* Bb = diag ? Ab : (B_s + buf * (32 * CH_STRIDE));

        if (ch < 3) {
            const int kc = (ch + 1) * 128;
            #pragma unroll
            for (int j = 0; j < 2; j++) {
                ra[j] = *reinterpret_cast<const float4*>(pa[j] + kc);
                if (!diag) rb[j] = *reinterpret_cast<const float4*>(pb[j] + kc);
            }
        }

        const float* a0 = Ab + r0 * CH_STRIDE + 32 * q;
        const float* a1 = a0 + 16 * CH_STRIDE;
        const float* b0 = Bb + cb * CH_STRIDE + 32 * q;
        const float* b1 = b0 + CH_STRIDE;
        const float* b2 = b1 + CH_STRIDE;
        const float* b3 = b2 + CH_STRIDE;

        #pragma unroll
        for (int k = 0; k < 32; k += 4) {
            ulonglong2 aL = *reinterpret_cast<const ulonglong2*>(a0 + k);
            ulonglong2 aH = *reinterpret_cast<const ulonglong2*>(a1 + k);
            ulonglong2 q0 = *reinterpret_cast<const ulonglong2*>(b0 + k);
            ulonglong2 q1 = *reinterpret_cast<const ulonglong2*>(b1 + k);
            ulonglong2 q2 = *reinterpret_cast<const ulonglong2*>(b2 + k);
            ulonglong2 q3 = *reinterpret_cast<const ulonglong2*>(b3 + k);

            ffma2(acc[0], aL.x, q0.x); ffma2(acc[0], aL.y, q0.y);
            ffma2(acc[1], aL.x, q1.x); ffma2(acc[1], aL.y, q1.y);
            ffma2(acc[2], aL.x, q2.x); ffma2(acc[2], aL.y, q2.y);
            ffma2(acc[3], aL.x, q3.x); ffma2(acc[3], aL.y, q3.y);
            ffma2(acc[4], aH.x, q0.x); ffma2(acc[4], aH.y, q0.y);
            ffma2(acc[5], aH.x, q1.x); ffma2(acc[5], aH.y, q1.y);
            ffma2(acc[6], aH.x, q2.x); ffma2(acc[6], aH.y, q2.y);
            ffma2(acc[7], aH.x, q3.x); ffma2(acc[7], aH.y, q3.y);
        }

        if (ch < 3) {
            __syncthreads();
            const int nb = (ch + 1) & 1;
            float* An = A_s + nb * (32 * CH_STRIDE);
            float* Bn = B_s + nb * (32 * CH_STRIDE);
            #pragma unroll
            for (int j = 0; j < 2; j++) {
                *reinterpret_cast<float4*>(An + srow[j] * CH_STRIDE + scol[j]) = ra[j];
                if (!diag)
                    *reinterpret_cast<float4*>(Bn + srow[j] * CH_STRIDE + scol[j]) = rb[j];
            }
            __syncthreads();
        }
    }

    #pragma unroll
    for (int rr = 0; rr < 2; rr++) {
        #pragma unroll
        for (int cc = 0; cc < 4; cc++) {
            float2 f = f2unpack(acc[rr * 4 + cc]);
            red[(q * 32 + r0 + 16 * rr) * 36 + cb + cc] = f.x + f.y;
        }
    }
    __syncthreads();

    float* S = sim + (long long)b * T_DIM * T_DIM;
    #pragma unroll
    for (int j = 0; j < 2; j++) {
        int o = tid + j * 512;
        int r = o >> 5, c = o & 31;
        float v = red[(r     ) * 36 + c] + red[(32 + r) * 36 + c]
                + red[(64 + r) * 36 + c] + red[(96 + r) * 36 + c];
        int gr = row0 + r, gc = col0 + c;
        if (gr < T_DIM && gc < T_DIM) {
            S[gr * T_DIM + gc] = v;
            S[gc * T_DIM + gr] = v;
        }
    }
}

// ---------------------------------------------------------------------------
// Kernel 3: band extraction + FC + ReLU (v3).
// 512 threads = (d in 128) x (q = s-quarter of 26). Weights read DIRECTLY
// from global (coalesced across d, L2-resident) — no smem staging.
// Band padded to s<104 with zeros -> compile-time 26-iter loop, fully
// unrolled, all LDG/LDS batched. Static smem ~11KB -> 4 blocks/SM.
// ---------------------------------------------------------------------------
__global__ __launch_bounds__(512) void k_fc(const float* __restrict__ sim,
                                            const float* __restrict__ fc_w,
                                            const float* __restrict__ fc_b,
                                            float* __restrict__ out) {
    __shared__ __align__(16) float band_t[104 * 8];   // [s][8], t 0..4 used
    __shared__ float scr[3 * TG * ODIM];

    const int b   = blockIdx.y;
    const int t0  = blockIdx.x * TG;
    const int tid = threadIdx.x;
    const int d   = tid & 127;
    const int q   = tid >> 7;

    // Band rows for the TG t's, padded with zeros for s in [101,104)
    const float* S = sim + (long long)b * T_DIM * T_DIM;
    for (int i = tid; i < TG * 104; i += 512) {
        int tt = i / 104, s = i - tt * 104;
        int t  = t0 + tt;
        int t2 = t + s - HALF;
        float v = 0.f;
        if (s < WIN && t2 >= 0 && t2 < T_DIM) v = S[t * T_DIM + t2];
        band_t[s * 8 + tt] = v;
    }
    __syncthreads();

    const int s0 = q * 26;

    unsigned long long acc2[2] = {0ull, 0ull};   // t pairs (0,1) (2,3)
    float acc4 = 0.f;                            // t 4

    const float* wp = fc_w + d;
    #pragma unroll
    for (int j = 0; j < 26; j++) {
        const int s = s0 + j;
        float wv = (s < WIN) ? __ldg(wp + s * ODIM) : 0.f;  // uniform predicate
        unsigned long long ww = f2pack(wv, wv);
        const float* bt = band_t + s * 8;
        ulonglong2 p01 = *reinterpret_cast<const ulonglong2*>(bt);  // t0..t3
        float b4 = bt[4];
        ffma2(acc2[0], ww, p01.x);
        ffma2(acc2[1], ww, p01.y);
        acc4 = fmaf(wv, b4, acc4);
    }

    float acc[TG];
    {
        float2 f0 = f2unpack(acc2[0]);
        float2 f1 = f2unpack(acc2[1]);
        acc[0] = f0.x; acc[1] = f0.y;
        acc[2] = f1.x; acc[3] = f1.y;
        acc[4] = acc4;
    }

    if (q) {
        float* sc = scr + (q - 1) * (TG * ODIM);
        #pragma unroll
        for (int tt = 0; tt < TG; tt++) sc[tt * ODIM + d] = acc[tt];
    }
    __syncthreads();

    if (q == 0) {
        const float bias = fc_b[d];
        float* O = out + ((long long)(b * T_DIM + t0)) * ODIM + d;
        #pragma unroll
        for (int tt = 0; tt < TG; tt++) {
            float v = acc[tt] + bias
                    + scr[0 * (TG*ODIM) + tt * ODIM + d]
                    + scr[1 * (TG*ODIM) + tt * ODIM + d]
                    + scr[2 * (TG*ODIM) + tt * ODIM + d];
            O[tt * ODIM] = fmaxf(v, 0.f);
        }
    }
}

// ---------------------------------------------------------------------------
extern "C" void kernel_launch(void* const* d_in, const int* in_sizes, int n_in,
                              void* d_out, int out_size) {
    const int*   frames = (const int*)  d_in[0];
    const float* fc_w   = (const float*)d_in[1];
    const float* fc_b   = (const float*)d_in[2];
    float*       out    = (float*)d_out;

    float* hist;
    float* sim;
    cudaGetSymbolAddress((void**)&hist, g_hist);
    cudaGetSymbolAddress((void**)&sim,  g_sim);

    cudaFuncSetAttribute(k_sim, cudaFuncAttributeMaxDynamicSharedMemorySize,
                         SIM_SMEM_BYTES);

    k_hist<<<B_DIM * T_DIM, 256>>>(frames, hist);
    k_sim <<<dim3(9, B_DIM), 512, SIM_SMEM_BYTES>>>(hist, sim);
    k_fc  <<<dim3(T_DIM / TG, B_DIM), 512>>>(sim, fc_w, fc_b, out);
}